// round 3
// baseline (speedup 1.0000x reference)
#include <cuda_runtime.h>
#include <math.h>

#define SEQ   2048
#define BATCH 2
#define HID   1024
#define NH    16
#define HD    64
#define MTOK  (BATCH*SEQ)   // 4096

// Scratch (allocation-free, per harness rules)
__device__ float g_Q[BATCH*NH*SEQ*HD];   // [b,h,n,d], pre-scaled by 1/8
__device__ float g_K[BATCH*NH*SEQ*HD];   // [b,h,n,d]
__device__ float g_V[BATCH*NH*SEQ*HD];   // [b,h,n,d]
__device__ float g_AO[MTOK*HID];         // [b,n,h*64+d]

// ---------------------------------------------------------------------------
// Kernel 1: QKV GEMM  C[4096,3072] = enc[4096,1024] @ W_attn[1024,3072] + b
// Epilogue scatters into head-major Q (scaled), K, V buffers.
// 128x128 tile, BK=8, 256 threads, 8x8 per thread (4+4 split, conflict-free).
// ---------------------------------------------------------------------------
__global__ __launch_bounds__(256) void qkv_gemm(const float* __restrict__ A,
                                                const float* __restrict__ B,
                                                const float* __restrict__ bias)
{
    const int K = HID, N = 3*HID;
    __shared__ float As[8][128];
    __shared__ float Bs[8][128];
    const int tid = threadIdx.x;
    const int tx = tid & 15, ty = tid >> 4;
    const int aRow = tid >> 1, aCol = (tid & 1) << 2;
    const int bRow = tid >> 5, bCol = (tid & 31) << 2;
    const float* Ag = A + (size_t)(blockIdx.y * 128) * K;
    const float* Bg = B + blockIdx.x * 128;

    float acc[8][8];
#pragma unroll
    for (int i = 0; i < 8; i++)
#pragma unroll
        for (int j = 0; j < 8; j++) acc[i][j] = 0.0f;

    for (int k0 = 0; k0 < K; k0 += 8) {
        float4 av = *(const float4*)(Ag + aRow*K + k0 + aCol);
        As[aCol+0][aRow] = av.x; As[aCol+1][aRow] = av.y;
        As[aCol+2][aRow] = av.z; As[aCol+3][aRow] = av.w;
        *(float4*)&Bs[bRow][bCol] = *(const float4*)(Bg + (size_t)(k0+bRow)*N + bCol);
        __syncthreads();
#pragma unroll
        for (int kk = 0; kk < 8; kk++) {
            float4 a0 = *(float4*)&As[kk][ty*4];
            float4 a1 = *(float4*)&As[kk][ty*4 + 64];
            float4 b0 = *(float4*)&Bs[kk][tx*4];
            float4 b1 = *(float4*)&Bs[kk][tx*4 + 64];
            float ra[8] = {a0.x,a0.y,a0.z,a0.w,a1.x,a1.y,a1.z,a1.w};
            float rb[8] = {b0.x,b0.y,b0.z,b0.w,b1.x,b1.y,b1.z,b1.w};
#pragma unroll
            for (int i = 0; i < 8; i++)
#pragma unroll
                for (int j = 0; j < 8; j++)
                    acc[i][j] = fmaf(ra[i], rb[j], acc[i][j]);
        }
        __syncthreads();
    }

#pragma unroll
    for (int i = 0; i < 8; i++) {
        int m  = blockIdx.y*128 + (i>>2)*64 + ty*4 + (i&3);
        int bb = m >> 11;          // / SEQ
        int n  = m & (SEQ-1);
#pragma unroll
        for (int j = 0; j < 8; j++) {
            int c = blockIdx.x*128 + (j>>2)*64 + tx*4 + (j&3);
            float v = acc[i][j] + bias[c];
            int part = c >> 10;            // 0:Q 1:K 2:V
            int h = (c >> 6) & 15;
            int l = c & 63;
            int dst = ((bb*NH + h)*SEQ + n)*HD + l;
            if (part == 0)      g_Q[dst] = v * 0.125f;   // 1/sqrt(64)
            else if (part == 1) g_K[dst] = v;
            else                g_V[dst] = v;
        }
    }
}

// ---------------------------------------------------------------------------
// Kernel 2: causal flash attention, fp32.
// Block = 64 queries of one (b,h). 256 threads as 16x16: thread (tq,tk) owns
// S[q0..q0+3][k0..k0+3] and O[q0..q0+3][d0..d0+3], d0 = tk*4.
// Online softmax over key tiles; row stats reduced across the 16-thread group.
// ---------------------------------------------------------------------------
#define PAD 65
__global__ __launch_bounds__(256) void attn_kernel(float* __restrict__ AO)
{
    extern __shared__ float sm[];
    float* Qs = sm;               // [64][65]
    float* Ks = Qs + 64*PAD;      // [64][65]
    float* Vs = Ks + 64*PAD;      // [64][65]
    float* Ps = Vs + 64*PAD;      // [64][65]

    const int qt = blockIdx.x, h = blockIdx.y, b = blockIdx.z;
    const int bh = b*NH + h;
    const float* Qg = g_Q + ((size_t)bh*SEQ + qt*64)*HD;
    const float* Kg = g_K + (size_t)bh*SEQ*HD;
    const float* Vg = g_V + (size_t)bh*SEQ*HD;

    const int tid = threadIdx.x;
    const int tk = tid & 15, tq = tid >> 4;
    const int q0 = tq*4, k0 = tk*4, d0 = tk*4;

    // Load Q tile (coalesced float4 from global, scalar smem stores)
#pragma unroll
    for (int t = 0; t < 4; t++) {
        int idx = t*256 + tid;
        int r = idx >> 4, c4 = (idx & 15) << 2;
        float4 v = *(const float4*)(Qg + r*HD + c4);
        Qs[r*PAD + c4+0] = v.x; Qs[r*PAD + c4+1] = v.y;
        Qs[r*PAD + c4+2] = v.z; Qs[r*PAD + c4+3] = v.w;
    }

    float mrow[4], lrow[4], O[4][4];
#pragma unroll
    for (int i = 0; i < 4; i++) {
        mrow[i] = -1e30f; lrow[i] = 0.0f;
#pragma unroll
        for (int j = 0; j < 4; j++) O[i][j] = 0.0f;
    }
    __syncthreads();

    for (int kt = 0; kt <= qt; kt++) {
        // Load K,V tiles
        const float* Kt = Kg + (size_t)kt*64*HD;
        const float* Vt = Vg + (size_t)kt*64*HD;
#pragma unroll
        for (int t = 0; t < 4; t++) {
            int idx = t*256 + tid;
            int r = idx >> 4, c4 = (idx & 15) << 2;
            float4 kv = *(const float4*)(Kt + r*HD + c4);
            Ks[r*PAD + c4+0] = kv.x; Ks[r*PAD + c4+1] = kv.y;
            Ks[r*PAD + c4+2] = kv.z; Ks[r*PAD + c4+3] = kv.w;
            float4 vv = *(const float4*)(Vt + r*HD + c4);
            Vs[r*PAD + c4+0] = vv.x; Vs[r*PAD + c4+1] = vv.y;
            Vs[r*PAD + c4+2] = vv.z; Vs[r*PAD + c4+3] = vv.w;
        }
        __syncthreads();

        // S = Q . K^T  (Q pre-scaled)
        float s[4][4];
#pragma unroll
        for (int i = 0; i < 4; i++)
#pragma unroll
            for (int j = 0; j < 4; j++) s[i][j] = 0.0f;
#pragma unroll 8
        for (int d = 0; d < HD; d++) {
            float qr[4], kr[4];
#pragma unroll
            for (int i = 0; i < 4; i++) qr[i] = Qs[(q0+i)*PAD + d];
#pragma unroll
            for (int j = 0; j < 4; j++) kr[j] = Ks[(k0+j)*PAD + d];
#pragma unroll
            for (int i = 0; i < 4; i++)
#pragma unroll
                for (int j = 0; j < 4; j++)
                    s[i][j] = fmaf(qr[i], kr[j], s[i][j]);
        }

        // Causal mask on diagonal tile: keep key <= query
        if (kt == qt) {
#pragma unroll
            for (int i = 0; i < 4; i++)
#pragma unroll
                for (int j = 0; j < 4; j++)
                    if (k0 + j > q0 + i) s[i][j] = -1e30f;
        }

        // Online softmax: row max / row sum over the 16-thread key group
        float rmax[4], rsum[4];
#pragma unroll
        for (int i = 0; i < 4; i++) {
            float v = fmaxf(fmaxf(s[i][0], s[i][1]), fmaxf(s[i][2], s[i][3]));
#pragma unroll
            for (int off = 8; off >= 1; off >>= 1)
                v = fmaxf(v, __shfl_xor_sync(0xffffffffu, v, off, 16));
            rmax[i] = v;
        }
#pragma unroll
        for (int i = 0; i < 4; i++) {
            float mn = fmaxf(mrow[i], rmax[i]);
            float alpha = __expf(mrow[i] - mn);
#pragma unroll
            for (int j = 0; j < 4; j++) s[i][j] = __expf(s[i][j] - mn);
            float v = s[i][0] + s[i][1] + s[i][2] + s[i][3];
#pragma unroll
            for (int off = 8; off >= 1; off >>= 1)
                v += __shfl_xor_sync(0xffffffffu, v, off, 16);
            rsum[i] = v;
            lrow[i] = lrow[i]*alpha + rsum[i];
            mrow[i] = mn;
#pragma unroll
            for (int j = 0; j < 4; j++) O[i][j] *= alpha;
        }

        // Stage P to shared
#pragma unroll
        for (int i = 0; i < 4; i++)
#pragma unroll
            for (int j = 0; j < 4; j++)
                Ps[(q0+i)*PAD + k0 + j] = s[i][j];
        __syncthreads();

        // O += P . V
#pragma unroll 8
        for (int k = 0; k < 64; k++) {
            float pr[4], vr[4];
#pragma unroll
            for (int i = 0; i < 4; i++) pr[i] = Ps[(q0+i)*PAD + k];
#pragma unroll
            for (int j = 0; j < 4; j++) vr[j] = Vs[k*PAD + d0 + j];
#pragma unroll
            for (int i = 0; i < 4; i++)
#pragma unroll
                for (int j = 0; j < 4; j++)
                    O[i][j] = fmaf(pr[i], vr[j], O[i][j]);
        }
        __syncthreads();
    }

    // Normalize + write [b, n, h*64+d]
#pragma unroll
    for (int i = 0; i < 4; i++) {
        float inv = 1.0f / lrow[i];
        int qglob = qt*64 + q0 + i;
        float* dst = AO + ((size_t)(b*SEQ + qglob))*HID + h*HD + d0;
#pragma unroll
        for (int j = 0; j < 4; j++) dst[j] = O[i][j] * inv;
    }
}

// ---------------------------------------------------------------------------
// Kernel 3: output projection  out[4096,1024] = AO @ W_out + b_out
// ---------------------------------------------------------------------------
__global__ __launch_bounds__(256) void out_gemm(const float* __restrict__ A,
                                                const float* __restrict__ B,
                                                const float* __restrict__ bias,
                                                float* __restrict__ C)
{
    const int K = HID, N = HID;
    __shared__ float As[8][128];
    __shared__ float Bs[8][128];
    const int tid = threadIdx.x;
    const int tx = tid & 15, ty = tid >> 4;
    const int aRow = tid >> 1, aCol = (tid & 1) << 2;
    const int bRow = tid >> 5, bCol = (tid & 31) << 2;
    const float* Ag = A + (size_t)(blockIdx.y * 128) * K;
    const float* Bg = B + blockIdx.x * 128;

    float acc[8][8];
#pragma unroll
    for (int i = 0; i < 8; i++)
#pragma unroll
        for (int j = 0; j < 8; j++) acc[i][j] = 0.0f;

    for (int k0 = 0; k0 < K; k0 += 8) {
        float4 av = *(const float4*)(Ag + aRow*K + k0 + aCol);
        As[aCol+0][aRow] = av.x; As[aCol+1][aRow] = av.y;
        As[aCol+2][aRow] = av.z; As[aCol+3][aRow] = av.w;
        *(float4*)&Bs[bRow][bCol] = *(const float4*)(Bg + (size_t)(k0+bRow)*N + bCol);
        __syncthreads();
#pragma unroll
        for (int kk = 0; kk < 8; kk++) {
            float4 a0 = *(float4*)&As[kk][ty*4];
            float4 a1 = *(float4*)&As[kk][ty*4 + 64];
            float4 b0 = *(float4*)&Bs[kk][tx*4];
            float4 b1 = *(float4*)&Bs[kk][tx*4 + 64];
            float ra[8] = {a0.x,a0.y,a0.z,a0.w,a1.x,a1.y,a1.z,a1.w};
            float rb[8] = {b0.x,b0.y,b0.z,b0.w,b1.x,b1.y,b1.z,b1.w};
#pragma unroll
            for (int i = 0; i < 8; i++)
#pragma unroll
                for (int j = 0; j < 8; j++)
                    acc[i][j] = fmaf(ra[i], rb[j], acc[i][j]);
        }
        __syncthreads();
    }

#pragma unroll
    for (int i = 0; i < 8; i++) {
        int m = blockIdx.y*128 + (i>>2)*64 + ty*4 + (i&3);
#pragma unroll
        for (int j = 0; j < 8; j++) {
            int c = blockIdx.x*128 + (j>>2)*64 + tx*4 + (j&3);
            C[(size_t)m*N + c] = acc[i][j] + bias[c];
        }
    }
}

// ---------------------------------------------------------------------------
extern "C" void kernel_launch(void* const* d_in, const int* in_sizes, int n_in,
                              void* d_out, int out_size)
{
    const float* enc    = (const float*)d_in[0];  // [2,2048,1024]
    const float* W_attn = (const float*)d_in[1];  // [1024,3072]
    const float* b_attn = (const float*)d_in[2];  // [3072]
    const float* W_out  = (const float*)d_in[3];  // [1024,1024]
    const float* b_out  = (const float*)d_in[4];  // [1024]
    float* out = (float*)d_out;                   // [2,2048,1024]

    float* d_AO = nullptr;
    cudaGetSymbolAddress((void**)&d_AO, g_AO);

    // 1) QKV projection + head-major scatter
    {
        dim3 grid(3*HID/128, MTOK/128);  // 24 x 32
        qkv_gemm<<<grid, 256>>>(enc, W_attn, b_attn);
    }

    // 2) causal attention
    {
        size_t smem = (size_t)4 * 64 * PAD * sizeof(float);  // 66560 B
        cudaFuncSetAttribute(attn_kernel,
                             cudaFuncAttributeMaxDynamicSharedMemorySize,
                             (int)smem);
        dim3 grid(SEQ/64, NH, BATCH);    // 32 x 16 x 2
        attn_kernel<<<grid, 256, smem>>>(d_AO);
    }

    // 3) output projection
    {
        dim3 grid(HID/128, MTOK/128);    // 8 x 32
        out_gemm<<<grid, 256>>>(d_AO, W_out, b_out, out);
    }
}

// round 6
// speedup vs baseline: 1.0969x; 1.0969x over previous
#include <cuda_runtime.h>
#include <math.h>

#define SEQ   2048
#define BATCH 2
#define HID   1024
#define NH    16
#define HD    64
#define MTOK  (BATCH*SEQ)   // 4096

// Scratch (allocation-free, per harness rules)
__device__ float g_Q[BATCH*NH*SEQ*HD];   // [b,h,n,d], pre-scaled by 1/8
__device__ float g_K[BATCH*NH*SEQ*HD];   // [b,h,n,d]
__device__ float g_V[BATCH*NH*SEQ*HD];   // [b,h,n,d]
__device__ float g_AO[MTOK*HID];         // [b,n,h*64+d]

// ---------------------------------------------------------------------------
// Kernel 1: QKV GEMM  C[4096,3072] = enc[4096,1024] @ W_attn[1024,3072] + b
// 128x128 tile, BK=16, double-buffered smem with register prefetch.
// 256 threads, 8x8 per thread (4+4 split). Epilogue scatters to Q/K/V.
// ---------------------------------------------------------------------------
__global__ __launch_bounds__(256, 2) void qkv_gemm(const float* __restrict__ A,
                                                   const float* __restrict__ B,
                                                   const float* __restrict__ bias)
{
    const int K = HID, N = 3*HID;
    __shared__ float As[2][16][128];
    __shared__ float Bs[2][16][128];
    const int tid = threadIdx.x;
    const int tx = tid & 15, ty = tid >> 4;
    const int aRow = tid >> 1, aCol = (tid & 1) << 3;   // 8 cols per thread
    const int bRow = tid >> 4, bCol = (tid & 15) << 2;  // + mirror at +64
    const float* Ag = A + (size_t)(blockIdx.y * 128) * K;
    const float* Bg = B + blockIdx.x * 128;

    float acc[8][8];
#pragma unroll
    for (int i = 0; i < 8; i++)
#pragma unroll
        for (int j = 0; j < 8; j++) acc[i][j] = 0.0f;

    // preload tile 0
    float4 pa0 = *(const float4*)(Ag + aRow*K + aCol);
    float4 pa1 = *(const float4*)(Ag + aRow*K + aCol + 4);
    float4 pb0 = *(const float4*)(Bg + (size_t)bRow*N + bCol);
    float4 pb1 = *(const float4*)(Bg + (size_t)bRow*N + bCol + 64);
    As[0][aCol+0][aRow]=pa0.x; As[0][aCol+1][aRow]=pa0.y;
    As[0][aCol+2][aRow]=pa0.z; As[0][aCol+3][aRow]=pa0.w;
    As[0][aCol+4][aRow]=pa1.x; As[0][aCol+5][aRow]=pa1.y;
    As[0][aCol+6][aRow]=pa1.z; As[0][aCol+7][aRow]=pa1.w;
    *(float4*)&Bs[0][bRow][bCol]    = pb0;
    *(float4*)&Bs[0][bRow][bCol+64] = pb1;
    __syncthreads();

    int buf = 0;
    const int NT = K/16;  // 64
    for (int kt = 0; kt < NT; kt++) {
        if (kt < NT-1) {
            const float* Ap = Ag + aRow*K + (kt+1)*16 + aCol;
            pa0 = *(const float4*)Ap;
            pa1 = *(const float4*)(Ap + 4);
            const float* Bp = Bg + (size_t)((kt+1)*16 + bRow)*N + bCol;
            pb0 = *(const float4*)Bp;
            pb1 = *(const float4*)(Bp + 64);
        }
#pragma unroll
        for (int kk = 0; kk < 16; kk++) {
            float4 a0 = *(float4*)&As[buf][kk][ty*4];
            float4 a1 = *(float4*)&As[buf][kk][ty*4 + 64];
            float4 b0 = *(float4*)&Bs[buf][kk][tx*4];
            float4 b1 = *(float4*)&Bs[buf][kk][tx*4 + 64];
            float ra[8] = {a0.x,a0.y,a0.z,a0.w,a1.x,a1.y,a1.z,a1.w};
            float rb[8] = {b0.x,b0.y,b0.z,b0.w,b1.x,b1.y,b1.z,b1.w};
#pragma unroll
            for (int i = 0; i < 8; i++)
#pragma unroll
                for (int j = 0; j < 8; j++)
                    acc[i][j] = fmaf(ra[i], rb[j], acc[i][j]);
        }
        if (kt < NT-1) {
            int nb = buf ^ 1;
            As[nb][aCol+0][aRow]=pa0.x; As[nb][aCol+1][aRow]=pa0.y;
            As[nb][aCol+2][aRow]=pa0.z; As[nb][aCol+3][aRow]=pa0.w;
            As[nb][aCol+4][aRow]=pa1.x; As[nb][aCol+5][aRow]=pa1.y;
            As[nb][aCol+6][aRow]=pa1.z; As[nb][aCol+7][aRow]=pa1.w;
            *(float4*)&Bs[nb][bRow][bCol]    = pb0;
            *(float4*)&Bs[nb][bRow][bCol+64] = pb1;
            __syncthreads();
            buf = nb;
        }
    }

#pragma unroll
    for (int i = 0; i < 8; i++) {
        int m  = blockIdx.y*128 + (i>>2)*64 + ty*4 + (i&3);
        int bb = m >> 11;          // / SEQ
        int n  = m & (SEQ-1);
#pragma unroll
        for (int j = 0; j < 8; j++) {
            int c = blockIdx.x*128 + (j>>2)*64 + tx*4 + (j&3);
            float v = acc[i][j] + bias[c];
            int part = c >> 10;            // 0:Q 1:K 2:V
            int h = (c >> 6) & 15;
            int l = c & 63;
            int dst = ((bb*NH + h)*SEQ + n)*HD + l;
            if (part == 0)      g_Q[dst] = v * 0.125f;   // 1/sqrt(64)
            else if (part == 1) g_K[dst] = v;
            else                g_V[dst] = v;
        }
    }
}

// ---------------------------------------------------------------------------
// Kernel 2: causal flash attention, fp32, transposed smem tiles so inner
// loops are 2x LDS.128 per 16 FFMA (was 8x LDS.32 per 16 FFMA).
// Block = 64 queries of one (b,h). 256 threads as 16x16.
// ---------------------------------------------------------------------------
#define APAD 68   // multiple of 4 -> float4-aligned rows
__global__ __launch_bounds__(256) void attn_kernel(float* __restrict__ AO)
{
    extern __shared__ float sm[];
    float* QsT = sm;                // [d][q]  64x68
    float* KsT = QsT + 64*APAD;     // [d][k]
    float* Vs  = KsT + 64*APAD;     // [k][d]  row-major
    float* PsT = Vs  + 64*APAD;     // [k][q]

    const int qt = blockIdx.x, h = blockIdx.y, b = blockIdx.z;
    const int bh = b*NH + h;
    const float* Qg = g_Q + ((size_t)bh*SEQ + qt*64)*HD;
    const float* Kg = g_K + (size_t)bh*SEQ*HD;
    const float* Vg = g_V + (size_t)bh*SEQ*HD;

    const int tid = threadIdx.x;
    const int tk = tid & 15, tq = tid >> 4;
    const int q0 = tq*4, k0 = tk*4, d0 = tk*4;

    // Load Q tile transposed: QsT[d][q]
#pragma unroll
    for (int t = 0; t < 4; t++) {
        int idx = t*256 + tid;
        int r = idx >> 4, c4 = (idx & 15) << 2;
        float4 v = *(const float4*)(Qg + r*HD + c4);
        QsT[(c4+0)*APAD + r] = v.x; QsT[(c4+1)*APAD + r] = v.y;
        QsT[(c4+2)*APAD + r] = v.z; QsT[(c4+3)*APAD + r] = v.w;
    }

    float mrow[4], lrow[4], O[4][4];
#pragma unroll
    for (int i = 0; i < 4; i++) {
        mrow[i] = -1e30f; lrow[i] = 0.0f;
#pragma unroll
        for (int j = 0; j < 4; j++) O[i][j] = 0.0f;
    }
    __syncthreads();

    for (int kt = 0; kt <= qt; kt++) {
        const float* Kt = Kg + (size_t)kt*64*HD;
        const float* Vt = Vg + (size_t)kt*64*HD;
#pragma unroll
        for (int t = 0; t < 4; t++) {
            int idx = t*256 + tid;
            int r = idx >> 4, c4 = (idx & 15) << 2;
            float4 kv = *(const float4*)(Kt + r*HD + c4);
            KsT[(c4+0)*APAD + r] = kv.x; KsT[(c4+1)*APAD + r] = kv.y;
            KsT[(c4+2)*APAD + r] = kv.z; KsT[(c4+3)*APAD + r] = kv.w;
            float4 vv = *(const float4*)(Vt + r*HD + c4);
            *(float4*)&Vs[r*APAD + c4] = vv;
        }
        __syncthreads();

        // S = Q . K^T   (Q pre-scaled by 1/8)
        float s[4][4];
#pragma unroll
        for (int i = 0; i < 4; i++)
#pragma unroll
            for (int j = 0; j < 4; j++) s[i][j] = 0.0f;
#pragma unroll 8
        for (int d = 0; d < HD; d++) {
            float4 qv = *(float4*)&QsT[d*APAD + q0];
            float4 kv = *(float4*)&KsT[d*APAD + k0];
            float qr[4] = {qv.x, qv.y, qv.z, qv.w};
            float kr[4] = {kv.x, kv.y, kv.z, kv.w};
#pragma unroll
            for (int i = 0; i < 4; i++)
#pragma unroll
                for (int j = 0; j < 4; j++)
                    s[i][j] = fmaf(qr[i], kr[j], s[i][j]);
        }

        // Causal mask on diagonal tile
        if (kt == qt) {
#pragma unroll
            for (int i = 0; i < 4; i++)
#pragma unroll
                for (int j = 0; j < 4; j++)
                    if (k0 + j > q0 + i) s[i][j] = -1e30f;
        }

        // Online softmax (16-lane key-group reductions)
#pragma unroll
        for (int i = 0; i < 4; i++) {
            float v = fmaxf(fmaxf(s[i][0], s[i][1]), fmaxf(s[i][2], s[i][3]));
#pragma unroll
            for (int off = 8; off >= 1; off >>= 1)
                v = fmaxf(v, __shfl_xor_sync(0xffffffffu, v, off, 16));
            float mn = fmaxf(mrow[i], v);
            float alpha = __expf(mrow[i] - mn);
#pragma unroll
            for (int j = 0; j < 4; j++) s[i][j] = __expf(s[i][j] - mn);
            float r = s[i][0] + s[i][1] + s[i][2] + s[i][3];
#pragma unroll
            for (int off = 8; off >= 1; off >>= 1)
                r += __shfl_xor_sync(0xffffffffu, r, off, 16);
            lrow[i] = lrow[i]*alpha + r;
            mrow[i] = mn;
#pragma unroll
            for (int j = 0; j < 4; j++) O[i][j] *= alpha;
        }

        // Stage P transposed: PsT[k][q]
#pragma unroll
        for (int j = 0; j < 4; j++)
#pragma unroll
            for (int i = 0; i < 4; i++)
                PsT[(k0+j)*APAD + q0 + i] = s[i][j];
        __syncthreads();

        // O += P . V
#pragma unroll 8
        for (int k = 0; k < 64; k++) {
            float4 pv = *(float4*)&PsT[k*APAD + q0];
            float4 vv = *(float4*)&Vs[k*APAD + d0];
            float pr[4] = {pv.x, pv.y, pv.z, pv.w};
            float vr[4] = {vv.x, vv.y, vv.z, vv.w};
#pragma unroll
            for (int i = 0; i < 4; i++)
#pragma unroll
                for (int j = 0; j < 4; j++)
                    O[i][j] = fmaf(pr[i], vr[j], O[i][j]);
        }
        __syncthreads();
    }

    // Normalize + write [b, n, h*64+d]
#pragma unroll
    for (int i = 0; i < 4; i++) {
        float inv = 1.0f / lrow[i];
        int qglob = qt*64 + q0 + i;
        float* dst = AO + ((size_t)(b*SEQ + qglob))*HID + h*HD + d0;
#pragma unroll
        for (int j = 0; j < 4; j++) dst[j] = O[i][j] * inv;
    }
}

// ---------------------------------------------------------------------------
// Kernel 3: output projection  out[4096,1024] = AO @ W_out + b_out
// Same double-buffered BK=16 scheme.
// ---------------------------------------------------------------------------
__global__ __launch_bounds__(256, 2) void out_gemm(const float* __restrict__ A,
                                                   const float* __restrict__ B,
                                                   const float* __restrict__ bias,
                                                   float* __restrict__ C)
{
    const int K = HID, N = HID;
    __shared__ float As[2][16][128];
    __shared__ float Bs[2][16][128];
    const int tid = threadIdx.x;
    const int tx = tid & 15, ty = tid >> 4;
    const int aRow = tid >> 1, aCol = (tid & 1) << 3;
    const int bRow = tid >> 4, bCol = (tid & 15) << 2;
    const float* Ag = A + (size_t)(blockIdx.y * 128) * K;
    const float* Bg = B + blockIdx.x * 128;

    float acc[8][8];
#pragma unroll
    for (int i = 0; i < 8; i++)
#pragma unroll
        for (int j = 0; j < 8; j++) acc[i][j] = 0.0f;

    float4 pa0 = *(const float4*)(Ag + aRow*K + aCol);
    float4 pa1 = *(const float4*)(Ag + aRow*K + aCol + 4);
    float4 pb0 = *(const float4*)(Bg + (size_t)bRow*N + bCol);
    float4 pb1 = *(const float4*)(Bg + (size_t)bRow*N + bCol + 64);
    As[0][aCol+0][aRow]=pa0.x; As[0][aCol+1][aRow]=pa0.y;
    As[0][aCol+2][aRow]=pa0.z; As[0][aCol+3][aRow]=pa0.w;
    As[0][aCol+4][aRow]=pa1.x; As[0][aCol+5][aRow]=pa1.y;
    As[0][aCol+6][aRow]=pa1.z; As[0][aCol+7][aRow]=pa1.w;
    *(float4*)&Bs[0][bRow][bCol]    = pb0;
    *(float4*)&Bs[0][bRow][bCol+64] = pb1;
    __syncthreads();

    int buf = 0;
    const int NT = K/16;
    for (int kt = 0; kt < NT; kt++) {
        if (kt < NT-1) {
            const float* Ap = Ag + aRow*K + (kt+1)*16 + aCol;
            pa0 = *(const float4*)Ap;
            pa1 = *(const float4*)(Ap + 4);
            const float* Bp = Bg + (size_t)((kt+1)*16 + bRow)*N + bCol;
            pb0 = *(const float4*)Bp;
            pb1 = *(const float4*)(Bp + 64);
        }
#pragma unroll
        for (int kk = 0; kk < 16; kk++) {
            float4 a0 = *(float4*)&As[buf][kk][ty*4];
            float4 a1 = *(float4*)&As[buf][kk][ty*4 + 64];
            float4 b0 = *(float4*)&Bs[buf][kk][tx*4];
            float4 b1 = *(float4*)&Bs[buf][kk][tx*4 + 64];
            float ra[8] = {a0.x,a0.y,a0.z,a0.w,a1.x,a1.y,a1.z,a1.w};
            float rb[8] = {b0.x,b0.y,b0.z,b0.w,b1.x,b1.y,b1.z,b1.w};
#pragma unroll
            for (int i = 0; i < 8; i++)
#pragma unroll
                for (int j = 0; j < 8; j++)
                    acc[i][j] = fmaf(ra[i], rb[j], acc[i][j]);
        }
        if (kt < NT-1) {
            int nb = buf ^ 1;
            As[nb][aCol+0][aRow]=pa0.x; As[nb][aCol+1][aRow]=pa0.y;
            As[nb][aCol+2][aRow]=pa0.z; As[nb][aCol+3][aRow]=pa0.w;
            As[nb][aCol+4][aRow]=pa1.x; As[nb][aCol+5][aRow]=pa1.y;
            As[nb][aCol+6][aRow]=pa1.z; As[nb][aCol+7][aRow]=pa1.w;
            *(float4*)&Bs[nb][bRow][bCol]    = pb0;
            *(float4*)&Bs[nb][bRow][bCol+64] = pb1;
            __syncthreads();
            buf = nb;
        }
    }

#pragma unroll
    for (int i = 0; i < 8; i++) {
        int m = blockIdx.y*128 + (i>>2)*64 + ty*4 + (i&3);
#pragma unroll
        for (int j = 0; j < 8; j++) {
            int c = blockIdx.x*128 + (j>>2)*64 + tx*4 + (j&3);
            C[(size_t)m*N + c] = acc[i][j] + bias[c];
        }
    }
}

// ---------------------------------------------------------------------------
extern "C" void kernel_launch(void* const* d_in, const int* in_sizes, int n_in,
                              void* d_out, int out_size)
{
    const float* enc    = (const float*)d_in[0];  // [2,2048,1024]
    const float* W_attn = (const float*)d_in[1];  // [1024,3072]
    const float* b_attn = (const float*)d_in[2];  // [3072]
    const float* W_out  = (const float*)d_in[3];  // [1024,1024]
    const float* b_out  = (const float*)d_in[4];  // [1024]
    float* out = (float*)d_out;                   // [2,2048,1024]

    float* d_AO = nullptr;
    cudaGetSymbolAddress((void**)&d_AO, g_AO);

    // 1) QKV projection + head-major scatter
    {
        dim3 grid(3*HID/128, MTOK/128);  // 24 x 32
        qkv_gemm<<<grid, 256>>>(enc, W_attn, b_attn);
    }

    // 2) causal attention
    {
        size_t smem = (size_t)4 * 64 * APAD * sizeof(float);  // 69632 B
        cudaFuncSetAttribute(attn_kernel,
                             cudaFuncAttributeMaxDynamicSharedMemorySize,
                             (int)smem);
        dim3 grid(SEQ/64, NH, BATCH);    // 32 x 16 x 2
        attn_kernel<<<grid, 256, smem>>>(d_AO);
    }

    // 3) output projection
    {
        dim3 grid(HID/128, MTOK/128);    // 8 x 32
        out_gemm<<<grid, 256>>>(d_AO, W_out, b_out, out);
    }
}